// round 1
// baseline (speedup 1.0000x reference)
#include <cuda_runtime.h>

#define BATCH 8
#define SEQ   2048
#define EMB   1024
#define HS    64
#define MROWS (BATCH*SEQ)   // 16384

typedef unsigned long long u64;

// Scratch for Q/K/V projections (device globals: no allocation allowed)
__device__ float g_Q[(size_t)MROWS * HS];
__device__ float g_K[(size_t)MROWS * HS];
__device__ float g_V[(size_t)MROWS * HS];

// ---- packed f32x2 helpers (Blackwell FFMA2 path; ptxas never emits this from C++) ----
__device__ __forceinline__ u64 pack2(float x, float y) {
    u64 r; asm("mov.b64 %0, {%1, %2};" : "=l"(r) : "f"(x), "f"(y)); return r;
}
__device__ __forceinline__ void unpack2(u64 a, float& x, float& y) {
    asm("mov.b64 {%0, %1}, %2;" : "=f"(x), "=f"(y) : "l"(a));
}
__device__ __forceinline__ u64 fma2(u64 a, u64 b, u64 c) {
    u64 d; asm("fma.rn.f32x2 %0, %1, %2, %3;" : "=l"(d) : "l"(a), "l"(b), "l"(c)); return d;
}
__device__ __forceinline__ u64 mul2(u64 a, u64 b) {
    u64 d; asm("mul.rn.f32x2 %0, %1, %2;" : "=l"(d) : "l"(a), "l"(b)); return d;
}

// ============================================================================
// Projection GEMM: Y[M,64] = X[M,1024] @ W[1024,64]
// blockIdx.y: 0 -> Q (from index), 1 -> K (from memory), 2 -> V (from memory)
// Tile: 128 rows x 64 cols, BK=16. 256 threads, each computes 8 rows x 4 cols
// as 4 row-pair x 4 col f32x2 accumulators.
// ============================================================================
__global__ __launch_bounds__(256) void proj_kernel(
    const float* __restrict__ Xq, const float* __restrict__ Xkv,
    const float* __restrict__ Wq, const float* __restrict__ Wk,
    const float* __restrict__ Wv)
{
    __shared__ float As[16][132];  // [k][row], transposed so row pairs are contiguous
    __shared__ float Bs[16][64];   // [k][col]

    const int tid = threadIdx.x;
    const int which = blockIdx.y;
    const float* X = (which == 0) ? Xq : Xkv;
    const float* W = (which == 0) ? Wq : ((which == 1) ? Wk : Wv);
    float* Y = (which == 0) ? g_Q : ((which == 1) ? g_K : g_V);

    const int row0 = blockIdx.x * 128;
    const int ty = tid >> 4;     // 0..15 -> row group of 8
    const int tx = tid & 15;     // 0..15 -> col group of 4

    u64 acc[4][4];
    #pragma unroll
    for (int i = 0; i < 4; i++)
        #pragma unroll
        for (int j = 0; j < 4; j++) acc[i][j] = 0ull;

    for (int k0 = 0; k0 < EMB; k0 += 16) {
        // Load A tile (128x16) transposed into smem
        #pragma unroll
        for (int i = 0; i < 2; i++) {
            int f  = tid + i * 256;        // 0..511 float4s
            int r  = f >> 2;               // row 0..127
            int kq = (f & 3) << 2;         // k 0,4,8,12
            float4 v = *(const float4*)(X + (size_t)(row0 + r) * EMB + k0 + kq);
            As[kq + 0][r] = v.x; As[kq + 1][r] = v.y;
            As[kq + 2][r] = v.z; As[kq + 3][r] = v.w;
        }
        // Load W tile (16x64)
        {
            int kk = tid >> 4;
            int c  = (tid & 15) << 2;
            *(float4*)&Bs[kk][c] = *(const float4*)(W + (size_t)(k0 + kk) * HS + c);
        }
        __syncthreads();

        #pragma unroll
        for (int kk = 0; kk < 16; kk++) {
            u64 a[4];
            #pragma unroll
            for (int i = 0; i < 4; i++)
                a[i] = *(const u64*)&As[kk][ty * 8 + 2 * i];   // packed row pair
            float4 b = *(const float4*)&Bs[kk][tx * 4];
            u64 bs[4] = { pack2(b.x, b.x), pack2(b.y, b.y),
                          pack2(b.z, b.z), pack2(b.w, b.w) };
            #pragma unroll
            for (int i = 0; i < 4; i++)
                #pragma unroll
                for (int j = 0; j < 4; j++)
                    acc[i][j] = fma2(a[i], bs[j], acc[i][j]);
        }
        __syncthreads();
    }

    // Write back: rows row0 + ty*8 + 2i (+1), cols tx*4..tx*4+3
    #pragma unroll
    for (int i = 0; i < 4; i++) {
        float r0v[4], r1v[4];
        #pragma unroll
        for (int j = 0; j < 4; j++) unpack2(acc[i][j], r0v[j], r1v[j]);
        *(float4*)(Y + (size_t)(row0 + ty * 8 + 2 * i) * HS + tx * 4) =
            make_float4(r0v[0], r0v[1], r0v[2], r0v[3]);
        *(float4*)(Y + (size_t)(row0 + ty * 8 + 2 * i + 1) * HS + tx * 4) =
            make_float4(r1v[0], r1v[1], r1v[2], r1v[3]);
    }
}

// ============================================================================
// Flash attention (causal): per block one 64-row q-tile of one batch.
// Online softmax; K and V share one smem buffer (phase-separated).
// Thread (ty,tx): 4 q-rows (ty*4..+3) x 4 h-cols / 4 keys (tx*4..+3).
// ============================================================================
__global__ __launch_bounds__(256) void attn_kernel(float* __restrict__ out)
{
    __shared__ float Qs [64][64];  // [d][row]   (transposed)
    __shared__ float KVs[64][64];  // K phase: [d][key]; V phase: [key][h]
    __shared__ float Ps [64][64];  // [row][key]

    const int tid = threadIdx.x;
    const int ty = tid >> 4;       // 0..15
    const int tx = tid & 15;       // 0..15
    const int ty4 = ty * 4, tx4 = tx * 4;
    const int b = blockIdx.y;
    const int bx = blockIdx.x;
    // balance: pair heavy/light q-tiles on consecutive blocks
    const int qt = (bx & 1) ? (31 - (bx >> 1)) : (bx >> 1);
    const int qrow0 = qt * 64;
    const float scale = 0.03125f;  // 1/sqrt(1024)

    // Load Q tile transposed: Qs[d][r]
    const float* Qg = g_Q + ((size_t)b * SEQ + qrow0) * HS;
    #pragma unroll
    for (int i = 0; i < 4; i++) {
        int f  = tid + i * 256;   // 0..1023 float4s
        int r  = f >> 4;          // 0..63
        int dq = (f & 15) << 2;   // 0..60
        float4 v = *(const float4*)(Qg + (size_t)r * HS + dq);
        Qs[dq + 0][r] = v.x; Qs[dq + 1][r] = v.y;
        Qs[dq + 2][r] = v.z; Qs[dq + 3][r] = v.w;
    }

    u64 o[4][2];                 // rows i, h-col pairs
    float m[4], l[4];
    #pragma unroll
    for (int i = 0; i < 4; i++) {
        o[i][0] = 0ull; o[i][1] = 0ull;
        m[i] = -1e30f; l[i] = 0.f;
    }

    for (int kt = 0; kt <= qt; kt++) {
        // ---- load K tile transposed: KVs[d][key] ----
        const float* Kg = g_K + ((size_t)b * SEQ + kt * 64) * HS;
        #pragma unroll
        for (int i = 0; i < 4; i++) {
            int f  = tid + i * 256;
            int r  = f >> 4;
            int dq = (f & 15) << 2;
            float4 v = *(const float4*)(Kg + (size_t)r * HS + dq);
            KVs[dq + 0][r] = v.x; KVs[dq + 1][r] = v.y;
            KVs[dq + 2][r] = v.z; KVs[dq + 3][r] = v.w;
        }
        __syncthreads();

        // ---- S = Q K^T (4 rows x 4 keys per thread, keys packed in f32x2) ----
        u64 s2[4][2];
        #pragma unroll
        for (int i = 0; i < 4; i++) { s2[i][0] = 0ull; s2[i][1] = 0ull; }

        #pragma unroll 8
        for (int d = 0; d < HS; d++) {
            float4 q = *(const float4*)&Qs[d][ty4];
            ulonglong2 k2 = *(const ulonglong2*)&KVs[d][tx4];
            u64 q0 = pack2(q.x, q.x), q1 = pack2(q.y, q.y);
            u64 q2 = pack2(q.z, q.z), q3 = pack2(q.w, q.w);
            s2[0][0] = fma2(q0, k2.x, s2[0][0]); s2[0][1] = fma2(q0, k2.y, s2[0][1]);
            s2[1][0] = fma2(q1, k2.x, s2[1][0]); s2[1][1] = fma2(q1, k2.y, s2[1][1]);
            s2[2][0] = fma2(q2, k2.x, s2[2][0]); s2[2][1] = fma2(q2, k2.y, s2[2][1]);
            s2[3][0] = fma2(q3, k2.x, s2[3][0]); s2[3][1] = fma2(q3, k2.y, s2[3][1]);
        }

        float s[4][4];
        #pragma unroll
        for (int i = 0; i < 4; i++) {
            unpack2(s2[i][0], s[i][0], s[i][1]);
            unpack2(s2[i][1], s[i][2], s[i][3]);
            #pragma unroll
            for (int j = 0; j < 4; j++) s[i][j] *= scale;
        }
        if (kt == qt) {  // diagonal tile: causal mask
            #pragma unroll
            for (int i = 0; i < 4; i++)
                #pragma unroll
                for (int j = 0; j < 4; j++)
                    if (tx4 + j > ty4 + i) s[i][j] = -1e30f;
        }

        // ---- online softmax ----
        #pragma unroll
        for (int i = 0; i < 4; i++) {
            float rm = fmaxf(fmaxf(s[i][0], s[i][1]), fmaxf(s[i][2], s[i][3]));
            rm = fmaxf(rm, __shfl_xor_sync(0xffffffffu, rm, 1));
            rm = fmaxf(rm, __shfl_xor_sync(0xffffffffu, rm, 2));
            rm = fmaxf(rm, __shfl_xor_sync(0xffffffffu, rm, 4));
            rm = fmaxf(rm, __shfl_xor_sync(0xffffffffu, rm, 8));
            float mn = fmaxf(m[i], rm);
            float corr = __expf(m[i] - mn);
            m[i] = mn;
            float p0 = __expf(s[i][0] - mn);
            float p1 = __expf(s[i][1] - mn);
            float p2 = __expf(s[i][2] - mn);
            float p3 = __expf(s[i][3] - mn);
            float rs = (p0 + p1) + (p2 + p3);
            rs += __shfl_xor_sync(0xffffffffu, rs, 1);
            rs += __shfl_xor_sync(0xffffffffu, rs, 2);
            rs += __shfl_xor_sync(0xffffffffu, rs, 4);
            rs += __shfl_xor_sync(0xffffffffu, rs, 8);
            l[i] = l[i] * corr + rs;
            u64 c2 = pack2(corr, corr);
            o[i][0] = mul2(o[i][0], c2);
            o[i][1] = mul2(o[i][1], c2);
            Ps[ty4 + i][tx4 + 0] = p0;
            Ps[ty4 + i][tx4 + 1] = p1;
            Ps[ty4 + i][tx4 + 2] = p2;
            Ps[ty4 + i][tx4 + 3] = p3;
        }
        __syncthreads();   // all K reads + P writes done

        // ---- load V tile (natural layout) into the shared KV buffer ----
        const float* Vg = g_V + ((size_t)b * SEQ + kt * 64) * HS;
        #pragma unroll
        for (int i = 0; i < 4; i++) {
            int f  = tid + i * 256;
            int r  = f >> 4;
            int dq = (f & 15) << 2;
            *(float4*)&KVs[r][dq] = *(const float4*)(Vg + (size_t)r * HS + dq);
        }
        __syncthreads();   // V + P visible

        // ---- O += P @ V ----
        #pragma unroll 8
        for (int k = 0; k < 64; k++) {
            ulonglong2 vv = *(const ulonglong2*)&KVs[k][tx4];
            #pragma unroll
            for (int i = 0; i < 4; i++) {
                float pv = Ps[ty4 + i][k];
                u64 p2v = pack2(pv, pv);
                o[i][0] = fma2(p2v, vv.x, o[i][0]);
                o[i][1] = fma2(p2v, vv.y, o[i][1]);
            }
        }
        __syncthreads();   // done with V before next K overwrite
    }

    // ---- epilogue: normalize and store ----
    #pragma unroll
    for (int i = 0; i < 4; i++) {
        float inv = 1.0f / l[i];
        float a0, a1, a2, a3;
        unpack2(o[i][0], a0, a1);
        unpack2(o[i][1], a2, a3);
        *(float4*)(out + ((size_t)b * SEQ + qrow0 + ty4 + i) * HS + tx4) =
            make_float4(a0 * inv, a1 * inv, a2 * inv, a3 * inv);
    }
}

extern "C" void kernel_launch(void* const* d_in, const int* in_sizes, int n_in,
                              void* d_out, int out_size)
{
    (void)in_sizes; (void)n_in; (void)out_size;
    const float* index  = (const float*)d_in[0];
    const float* memory = (const float*)d_in[1];
    const float* Wq     = (const float*)d_in[2];
    const float* Wk     = (const float*)d_in[3];
    const float* Wv     = (const float*)d_in[4];
    float* out = (float*)d_out;

    proj_kernel<<<dim3(MROWS / 128, 3), 256>>>(index, memory, Wq, Wk, Wv);
    attn_kernel<<<dim3(SEQ / 64, BATCH), 256>>>(out);
}